// round 1
// baseline (speedup 1.0000x reference)
#include <cuda_runtime.h>
#include <math.h>

#define NB 16
#define HH 512
#define WW 512
#define KR 15              // radius (kernel 31)
#define KKINV (1.0f/961.0f)
#define MUF 5.0f

// -------- scratch (no allocations allowed) --------
__device__ float g_vsum[NB * HH * WW];          // vertical box sums (16 MB)
__device__ float g_part[NB * HH * 4];           // per-(b,row) partials: {wbce_num, weit_sum, inter, union}
__device__ float g_batch[NB];                   // per-batch loss

// ================= Kernel A: vertical sliding box sum =================
#define RPB 32
__global__ void vert_kernel(const float* __restrict__ mask) {
    const int segs = HH / RPB;                  // 16
    int b  = blockIdx.x / segs;
    int r0 = (blockIdx.x % segs) * RPB;
    int c  = threadIdx.x;                       // 512 threads, one per column

    const float* mb = mask + (size_t)b * HH * WW;
    float* vb = g_vsum + (size_t)b * HH * WW;

    float s = 0.0f;
    int lo = r0 - KR; if (lo < 0) lo = 0;
    int hi = r0 + KR; if (hi > HH - 1) hi = HH - 1;
    #pragma unroll 4
    for (int j = lo; j <= hi; ++j) s += mb[j * WW + c];

    #pragma unroll
    for (int r = r0; r < r0 + RPB; ++r) {
        vb[r * WW + c] = s;
        int add = r + KR + 1;
        int sub = r - KR;
        if (add < HH) s += mb[add * WW + c];
        if (sub >= 0) s -= mb[sub * WW + c];
    }
}

// ================= Kernel B: horizontal box (prefix scan) + elementwise + reduce =================
// one block per (b, row); 128 threads, 4 consecutive columns per thread
__global__ void main_kernel(const float* __restrict__ pred,
                            const float* __restrict__ mask) {
    __shared__ float sP[WW];        // inclusive row prefix of vertical sums
    __shared__ float wsum[4];       // per-warp scan totals
    __shared__ float red[16];       // 4 warps x 4 accumulators

    int b = blockIdx.x >> 9;
    int r = blockIdx.x & (HH - 1);
    int t = threadIdx.x;            // 0..127
    int lane = t & 31;
    int wid  = t >> 5;
    int c0 = t * 4;

    const size_t rowOff = (size_t)b * HH * WW + (size_t)r * WW;
    const float4 v4 = *(const float4*)(g_vsum + rowOff + c0);

    // thread-local inclusive prefix
    float l0 = v4.x;
    float l1 = l0 + v4.y;
    float l2 = l1 + v4.z;
    float l3 = l2 + v4.w;
    float tot = l3;

    // warp inclusive scan of thread totals
    float x = tot;
    #pragma unroll
    for (int d = 1; d < 32; d <<= 1) {
        float n = __shfl_up_sync(0xffffffffu, x, d);
        if (lane >= d) x += n;
    }
    if (lane == 31) wsum[wid] = x;
    __syncthreads();
    float woff = 0.0f;
    #pragma unroll
    for (int w = 0; w < 4; ++w) if (w < wid) woff += wsum[w];
    float excl = woff + (x - tot);  // exclusive prefix for this thread's first column

    // store inclusive prefix values (float4 -> STS.128, conflict-free)
    float4 P4 = make_float4(excl + l0, excl + l1, excl + l2, excl + l3);
    *(float4*)(sP + c0) = P4;
    __syncthreads();

    // elementwise math + accumulation
    const float4 m4 = *(const float4*)(mask + rowOff + c0);
    const size_t predOff = (((size_t)b * 2 + 1) * HH + r) * WW;
    const float4 p4 = *(const float4*)(pred + predOff + c0);

    float a0 = 0.f, a1 = 0.f, a2 = 0.f, a3 = 0.f;
    float mv[4] = {m4.x, m4.y, m4.z, m4.w};
    float pv[4] = {p4.x, p4.y, p4.z, p4.w};

    #pragma unroll
    for (int i = 0; i < 4; ++i) {
        int c = c0 + i;
        int hiIdx = c + 15; if (hiIdx > WW - 1) hiIdx = WW - 1;
        float win = sP[hiIdx];
        if (c >= 16) win -= sP[c - 16];
        float box = win * KKINV;

        float m = mv[i];
        float p = pv[i];
        float weit = 1.0f + MUF * fabsf(box - m);

        float bce = fmaxf(p, 0.0f) - p * m + log1pf(__expf(-fabsf(p)));
        float ps  = 1.0f / (1.0f + __expf(-p));

        a0 += weit * bce;
        a1 += weit;
        a2 += ps * m * weit;
        a3 += (ps + m) * weit;
    }

    // deterministic block reduction: warp shuffle then thread 0 over 4 warps
    #pragma unroll
    for (int d = 16; d > 0; d >>= 1) {
        a0 += __shfl_down_sync(0xffffffffu, a0, d);
        a1 += __shfl_down_sync(0xffffffffu, a1, d);
        a2 += __shfl_down_sync(0xffffffffu, a2, d);
        a3 += __shfl_down_sync(0xffffffffu, a3, d);
    }
    if (lane == 0) {
        red[wid * 4 + 0] = a0;
        red[wid * 4 + 1] = a1;
        red[wid * 4 + 2] = a2;
        red[wid * 4 + 3] = a3;
    }
    __syncthreads();
    if (t == 0) {
        float s0 = red[0] + red[4] + red[8]  + red[12];
        float s1 = red[1] + red[5] + red[9]  + red[13];
        float s2 = red[2] + red[6] + red[10] + red[14];
        float s3 = red[3] + red[7] + red[11] + red[15];
        float4* gp = (float4*)g_part;
        gp[blockIdx.x] = make_float4(s0, s1, s2, s3);
    }
}

// ================= Kernel C: per-batch reduction of 512 row-partials =================
__global__ void batch_kernel() {
    __shared__ float red[16];
    int b = blockIdx.x;
    int t = threadIdx.x;            // 128 threads
    int lane = t & 31, wid = t >> 5;

    float a0 = 0.f, a1 = 0.f, a2 = 0.f, a3 = 0.f;
    const float4* gp = (const float4*)g_part;
    #pragma unroll
    for (int k = 0; k < 4; ++k) {
        float4 v = gp[b * HH + t + 128 * k];
        a0 += v.x; a1 += v.y; a2 += v.z; a3 += v.w;
    }
    #pragma unroll
    for (int d = 16; d > 0; d >>= 1) {
        a0 += __shfl_down_sync(0xffffffffu, a0, d);
        a1 += __shfl_down_sync(0xffffffffu, a1, d);
        a2 += __shfl_down_sync(0xffffffffu, a2, d);
        a3 += __shfl_down_sync(0xffffffffu, a3, d);
    }
    if (lane == 0) {
        red[wid * 4 + 0] = a0;
        red[wid * 4 + 1] = a1;
        red[wid * 4 + 2] = a2;
        red[wid * 4 + 3] = a3;
    }
    __syncthreads();
    if (t == 0) {
        float s0 = red[0] + red[4] + red[8]  + red[12];
        float s1 = red[1] + red[5] + red[9]  + red[13];
        float s2 = red[2] + red[6] + red[10] + red[14];
        float s3 = red[3] + red[7] + red[11] + red[15];
        float wbce = s0 / s1;
        float wiou = 1.0f - (s2 + 1.0f) / (s3 - s2 + 1.0f);
        g_batch[b] = wbce + wiou;
    }
}

// ================= Kernel D: final mean =================
__global__ void final_kernel(float* __restrict__ out) {
    int t = threadIdx.x;            // 32 threads
    float v = (t < NB) ? g_batch[t] : 0.0f;
    #pragma unroll
    for (int d = 16; d > 0; d >>= 1) v += __shfl_xor_sync(0xffffffffu, v, d);
    if (t == 0) out[0] = v * (1.0f / NB);
}

extern "C" void kernel_launch(void* const* d_in, const int* in_sizes, int n_in,
                              void* d_out, int out_size) {
    // pred: [16,2,512,512] = 8388608 elems; mask: [16,512,512] = 4194304 elems
    const float* pred = (const float*)d_in[0];
    const float* mask = (const float*)d_in[1];
    if (n_in >= 2 && in_sizes[0] == NB * HH * WW && in_sizes[1] == NB * 2 * HH * WW) {
        // defensive: swapped order
        mask = (const float*)d_in[0];
        pred = (const float*)d_in[1];
    }
    float* out = (float*)d_out;

    vert_kernel<<<NB * (HH / RPB), WW>>>(mask);
    main_kernel<<<NB * HH, 128>>>(pred, mask);
    batch_kernel<<<NB, 128>>>();
    final_kernel<<<1, 32>>>(out);
}